// round 1
// baseline (speedup 1.0000x reference)
#include <cuda_runtime.h>
#include <cuda_bf16.h>
#include <cstdint>

// Problem shapes (fixed by reference setup_inputs)
#define N_SEQ 256
#define M_GENES 2000
#define D_DIM 128
#define TABLE_ROWS (M_GENES * 4)   // 8000

// Scratch: reciprocal norms for each (gene, base) table row.
__device__ float g_inv_norm[TABLE_ROWS];

// ---------------------------------------------------------------------------
// Kernel 1: inv_norm[r] = 1 / max(||emb[r, :]||, 1e-12)
// One warp per table row: 32 lanes x float4 = 128 floats.
// ---------------------------------------------------------------------------
__global__ void norm_kernel(const float* __restrict__ emb) {
    int warp_in_block = threadIdx.x >> 5;
    int lane = threadIdx.x & 31;
    int row = blockIdx.x * (blockDim.x >> 5) + warp_in_block;
    if (row >= TABLE_ROWS) return;

    const float4* row4 = reinterpret_cast<const float4*>(emb + (size_t)row * D_DIM);
    float4 v = row4[lane];
    float ss = v.x * v.x + v.y * v.y + v.z * v.z + v.w * v.w;

    // warp reduce
    #pragma unroll
    for (int off = 16; off > 0; off >>= 1)
        ss += __shfl_xor_sync(0xFFFFFFFFu, ss, off);

    if (lane == 0) {
        float nrm = sqrtf(ss);
        g_inv_norm[row] = 1.0f / fmaxf(nrm, 1e-12f);
    }
}

// ---------------------------------------------------------------------------
// Kernel 2: gather + scale. One warp per output row (n, m).
// blockDim = 256 (8 warps -> 8 consecutive m per block), grid = (M/8, N).
// Each lane: one float4 load (L2-resident table) + one float4 store (HBM).
// ---------------------------------------------------------------------------
__global__ void __launch_bounds__(256, 8) gather_kernel(
    const int* __restrict__ gene_seq,       // (N, M)
    const float* __restrict__ emb,          // (M, 4, D)
    float* __restrict__ out)                // (N, M, D)
{
    const int warp_in_block = threadIdx.x >> 5;
    const int lane = threadIdx.x & 31;
    const int m = blockIdx.x * 8 + warp_in_block;   // grid.x = M/8 = 250 exact
    const int n = blockIdx.y;

    // Uniform per-warp index load (hardware broadcast)
    const int g = gene_seq[(size_t)n * M_GENES + m];
    const int trow = (m << 2) + g;

    const float inv = g_inv_norm[trow];

    const float4* src = reinterpret_cast<const float4*>(emb + (size_t)trow * D_DIM);
    float4 v = src[lane];
    v.x *= inv; v.y *= inv; v.z *= inv; v.w *= inv;

    float4* dst = reinterpret_cast<float4*>(out + ((size_t)n * M_GENES + m) * D_DIM);
    dst[lane] = v;
}

extern "C" void kernel_launch(void* const* d_in, const int* in_sizes, int n_in,
                              void* d_out, int out_size) {
    const int* gene_seq = (const int*)d_in[0];          // (256, 2000) int32
    const float* emb    = (const float*)d_in[1];        // (2000, 4, 128) fp32
    float* out          = (float*)d_out;                // (256, 2000, 128) fp32

    // Kernel 1: 8000 rows, 8 warps/block -> 1000 blocks
    norm_kernel<<<(TABLE_ROWS + 7) / 8, 256>>>(emb);

    // Kernel 2: 250 x 256 blocks, 256 threads
    dim3 grid(M_GENES / 8, N_SEQ, 1);
    gather_kernel<<<grid, 256>>>(gene_seq, emb, out);
}

// round 2
// speedup vs baseline: 1.0424x; 1.0424x over previous
#include <cuda_runtime.h>
#include <cuda_bf16.h>
#include <cstdint>

// Problem shapes (fixed by reference setup_inputs)
#define N_SEQ   256
#define M_GENES 2000
#define D_DIM   128
#define TABLE_ROWS (M_GENES * 4)   // 8000

#define M_TILE  8                  // genes per block
#define N_TILE  32                 // sequence positions per block

// Scratch: normalized embedding table, (2000, 4, 128) fp32 = 4 MB.
__device__ float g_table[TABLE_ROWS * D_DIM];

// ---------------------------------------------------------------------------
// Kernel 1: g_table[r,:] = emb[r,:] / max(||emb[r,:]||, 1e-12)
// One warp per table row: 32 lanes x float4 = 128 floats.
// ---------------------------------------------------------------------------
__global__ void __launch_bounds__(256) norm_kernel(const float* __restrict__ emb) {
    const int warp_in_block = threadIdx.x >> 5;
    const int lane = threadIdx.x & 31;
    const int row = blockIdx.x * 8 + warp_in_block;
    if (row >= TABLE_ROWS) return;

    const float4* src = reinterpret_cast<const float4*>(emb + (size_t)row * D_DIM);
    float4 v = src[lane];
    float ss = v.x * v.x + v.y * v.y + v.z * v.z + v.w * v.w;

    #pragma unroll
    for (int off = 16; off > 0; off >>= 1)
        ss += __shfl_xor_sync(0xFFFFFFFFu, ss, off);

    const float inv = 1.0f / fmaxf(sqrtf(ss), 1e-12f);
    v.x *= inv; v.y *= inv; v.z *= inv; v.w *= inv;

    float4* dst = reinterpret_cast<float4*>(g_table + (size_t)row * D_DIM);
    dst[lane] = v;
}

// ---------------------------------------------------------------------------
// Kernel 2: gather from SMEM-staged normalized table, streaming stores.
//   Block: 256 threads (8 warps). Tile: M_TILE=8 genes x N_TILE=32 positions.
//   - Stage 8 genes x 4 bases x 128 floats = 16 KB of g_table in SMEM.
//   - Stage the 32x8 gene_seq indices in SMEM.
//   - Warp w owns gene m0+w; loops over 32 n values: uniform idx LDS,
//     LDS.128 row fragment, STG.128 streaming store.
// ---------------------------------------------------------------------------
__global__ void __launch_bounds__(256, 6) gather_kernel(
    const int* __restrict__ gene_seq,       // (N, M)
    float* __restrict__ out)                // (N, M, D)
{
    __shared__ float4 tile[M_TILE * 4 * 32];     // 16 KB: [m_local*4+g][lane]
    __shared__ int    sg[N_TILE][M_TILE];        // 1 KB indices

    const int tid  = threadIdx.x;
    const int warp = tid >> 5;
    const int lane = tid & 31;
    const int m0 = blockIdx.x * M_TILE;          // grid.x = 250
    const int n0 = blockIdx.y * N_TILE;          // grid.y = 8

    // Stage table slab: 1024 float4, 256 threads -> 4 each (coalesced).
    const float4* tsrc = reinterpret_cast<const float4*>(g_table) + (size_t)m0 * 4 * 32;
    #pragma unroll
    for (int i = 0; i < 4; i++)
        tile[tid + i * 256] = tsrc[tid + i * 256];

    // Stage indices: thread tid -> (i = tid>>3 in n, j = tid&7 in m).
    {
        const int i = tid >> 3;
        const int j = tid & 7;
        sg[i][j] = gene_seq[(size_t)(n0 + i) * M_GENES + m0 + j];
    }
    __syncthreads();

    const int m = m0 + warp;
    float4* outb = reinterpret_cast<float4*>(out);

    #pragma unroll 8
    for (int nn = 0; nn < N_TILE; nn++) {
        const int g = sg[nn][warp];                       // uniform broadcast LDS
        const float4 v = tile[(warp * 4 + g) * 32 + lane];
        const size_t off = ((size_t)(n0 + nn) * M_GENES + m) * 32 + lane;
        __stcs(outb + off, v);                            // streaming 128-bit store
    }
}

extern "C" void kernel_launch(void* const* d_in, const int* in_sizes, int n_in,
                              void* d_out, int out_size) {
    const int* gene_seq = (const int*)d_in[0];      // (256, 2000) int32
    const float* emb    = (const float*)d_in[1];    // (2000, 4, 128) fp32
    float* out          = (float*)d_out;            // (256, 2000, 128) fp32

    norm_kernel<<<TABLE_ROWS / 8, 256>>>(emb);

    dim3 grid(M_GENES / M_TILE, N_SEQ / N_TILE, 1); // (250, 8)
    gather_kernel<<<grid, 256>>>(gene_seq, out);
}

// round 3
// speedup vs baseline: 1.5316x; 1.4692x over previous
#include <cuda_runtime.h>
#include <cuda_bf16.h>
#include <cstdint>

// Problem shapes (fixed by reference setup_inputs)
#define N_SEQ   256
#define M_GENES 2000
#define D_DIM   128

// Single fused kernel.
//   Block: 256 threads = 8 warps. Warp w owns gene m = blockIdx.x*8 + w.
//   Tile:  32 sequence positions (blockIdx.y), matching warp size.
//
//   Prologue (per warp, registers only):
//     - load the gene's 4 embedding rows (2 KB contiguous, 4x LDG.128)
//     - butterfly-reduce the 4 squared norms (result in every lane)
//     - scale rows in registers -> r0..r3 (16 regs)
//     - lane nn loads gene_seq[n0+nn][m] (one 4B LDG per lane)
//
//   Inner loop (32 iterations): shfl index broadcast, 4-way register
//   select, one streaming STG.128. No SMEM, no barriers, no second kernel.
//   Redundant normalization across the 8 y-blocks is ~32 MB of L2-hit
//   reads + trivial FLOPs — free against the 262 MB write wall.
__global__ void __launch_bounds__(256) fused_gene_embed_kernel(
    const int* __restrict__ gene_seq,      // (N, M)
    const float* __restrict__ emb,         // (M, 4, D)
    float* __restrict__ out)               // (N, M, D)
{
    const int warp = threadIdx.x >> 5;
    const int lane = threadIdx.x & 31;
    const int m  = blockIdx.x * 8 + warp;   // grid.x = 250 (exact)
    const int n0 = blockIdx.y * 32;         // grid.y = 8   (exact)

    // ---- load this gene's 4 table rows into registers ----
    const float4* src = reinterpret_cast<const float4*>(emb) + (size_t)m * 4 * 32;
    float4 r0 = src[lane];
    float4 r1 = src[32 + lane];
    float4 r2 = src[64 + lane];
    float4 r3 = src[96 + lane];

    // ---- per-lane sequence index (lane == nn within the 32-tile) ----
    const int gl = gene_seq[(size_t)(n0 + lane) * M_GENES + m];

    // ---- normalize rows in registers (butterfly keeps norm in all lanes) ----
    {
        float s0 = r0.x*r0.x + r0.y*r0.y + r0.z*r0.z + r0.w*r0.w;
        float s1 = r1.x*r1.x + r1.y*r1.y + r1.z*r1.z + r1.w*r1.w;
        float s2 = r2.x*r2.x + r2.y*r2.y + r2.z*r2.z + r2.w*r2.w;
        float s3 = r3.x*r3.x + r3.y*r3.y + r3.z*r3.z + r3.w*r3.w;
        #pragma unroll
        for (int off = 16; off > 0; off >>= 1) {
            s0 += __shfl_xor_sync(0xFFFFFFFFu, s0, off);
            s1 += __shfl_xor_sync(0xFFFFFFFFu, s1, off);
            s2 += __shfl_xor_sync(0xFFFFFFFFu, s2, off);
            s3 += __shfl_xor_sync(0xFFFFFFFFu, s3, off);
        }
        const float i0 = 1.0f / fmaxf(sqrtf(s0), 1e-12f);
        const float i1 = 1.0f / fmaxf(sqrtf(s1), 1e-12f);
        const float i2 = 1.0f / fmaxf(sqrtf(s2), 1e-12f);
        const float i3 = 1.0f / fmaxf(sqrtf(s3), 1e-12f);
        r0.x *= i0; r0.y *= i0; r0.z *= i0; r0.w *= i0;
        r1.x *= i1; r1.y *= i1; r1.z *= i1; r1.w *= i1;
        r2.x *= i2; r2.y *= i2; r2.z *= i2; r2.w *= i2;
        r3.x *= i3; r3.y *= i3; r3.z *= i3; r3.w *= i3;
    }

    // ---- pure streaming-store loop ----
    float4* ob = reinterpret_cast<float4*>(out)
               + ((size_t)n0 * M_GENES + m) * 32 + lane;
    const size_t row_stride = (size_t)M_GENES * 32;   // one n step

    #pragma unroll 8
    for (int nn = 0; nn < 32; nn++) {
        const int g = __shfl_sync(0xFFFFFFFFu, gl, nn);
        const float4 v = (g == 0) ? r0 : (g == 1) ? r1 : (g == 2) ? r2 : r3;
        __stcs(ob, v);
        ob += row_stride;
    }
}

extern "C" void kernel_launch(void* const* d_in, const int* in_sizes, int n_in,
                              void* d_out, int out_size) {
    const int* gene_seq = (const int*)d_in[0];      // (256, 2000) int32
    const float* emb    = (const float*)d_in[1];    // (2000, 4, 128) fp32
    float* out          = (float*)d_out;            // (256, 2000, 128) fp32

    dim3 grid(M_GENES / 8, N_SEQ / 32, 1);          // (250, 8)
    fused_gene_embed_kernel<<<grid, 256>>>(gene_seq, emb, out);
}